// round 1
// baseline (speedup 1.0000x reference)
#include <cuda_runtime.h>
#include <cstdint>

#define N_ROWS 32768
#define K_CB   4096
#define D_DIM  512

// Per-row packed (ordered-float << 32 | (K-1-col)) argmax accumulator.
__device__ unsigned long long g_rowmax[N_ROWS];

__device__ __forceinline__ unsigned int f2ord(float f) {
    unsigned int u = __float_as_uint(f);
    return (u & 0x80000000u) ? ~u : (u | 0x80000000u);
}

__global__ void init_rowmax_kernel() {
    int i = blockIdx.x * blockDim.x + threadIdx.x;
    if (i < N_ROWS) g_rowmax[i] = 0ull;
}

// C[n,k] = sum_d A[n,d] * B[k,d]; A=[N,512] row-major, B=[4096,512] row-major.
// 128x128 tile per CTA, 256 threads, 8x8 accumulators per thread, D staged in
// 16-wide smem chunks (transposed to [d][row] with +4 padding).
__global__ __launch_bounds__(256)
void gemm_argmax_kernel(const float* __restrict__ A,
                        const float* __restrict__ B,
                        float* __restrict__ C) {
    __shared__ float As[16][132];
    __shared__ float Bs[16][132];

    const int tid = threadIdx.x;
    const int tx = tid & 15;   // col group
    const int ty = tid >> 4;   // row group

    const int rowBase = blockIdx.y * 128;  // n
    const int colBase = blockIdx.x * 128;  // k

    float acc[8][8];
    #pragma unroll
    for (int i = 0; i < 8; i++)
        #pragma unroll
        for (int j = 0; j < 8; j++)
            acc[i][j] = 0.0f;

    for (int dk = 0; dk < D_DIM; dk += 16) {
        // Stage A tile: 128 rows x 16 d = 512 float4 loads, 2 per thread.
        #pragma unroll
        for (int l = 0; l < 2; l++) {
            int idx = tid + l * 256;       // 0..511
            int r   = idx >> 2;            // row in tile
            int c4  = idx & 3;             // float4 slot along d
            float4 v = *(const float4*)(A + (size_t)(rowBase + r) * D_DIM + dk + c4 * 4);
            As[c4 * 4 + 0][r] = v.x;
            As[c4 * 4 + 1][r] = v.y;
            As[c4 * 4 + 2][r] = v.z;
            As[c4 * 4 + 3][r] = v.w;
        }
        // Stage B tile likewise.
        #pragma unroll
        for (int l = 0; l < 2; l++) {
            int idx = tid + l * 256;
            int r   = idx >> 2;
            int c4  = idx & 3;
            float4 v = *(const float4*)(B + (size_t)(colBase + r) * D_DIM + dk + c4 * 4);
            Bs[c4 * 4 + 0][r] = v.x;
            Bs[c4 * 4 + 1][r] = v.y;
            Bs[c4 * 4 + 2][r] = v.z;
            Bs[c4 * 4 + 3][r] = v.w;
        }
        __syncthreads();

        #pragma unroll
        for (int dd = 0; dd < 16; dd++) {
            float ra[8], rb[8];
            #pragma unroll
            for (int i = 0; i < 8; i++) ra[i] = As[dd][ty * 8 + i];
            #pragma unroll
            for (int j = 0; j < 8; j++) rb[j] = Bs[dd][tx * 8 + j];
            #pragma unroll
            for (int i = 0; i < 8; i++)
                #pragma unroll
                for (int j = 0; j < 8; j++)
                    acc[i][j] = fmaf(ra[i], rb[j], acc[i][j]);
        }
        __syncthreads();
    }

    // Epilogue: store logits + fused per-row argmax.
    #pragma unroll
    for (int i = 0; i < 8; i++) {
        const int rowT = ty * 8 + i;            // row within tile
        const int row  = rowBase + rowT;        // global n
        float* cptr = C + (size_t)row * K_CB + colBase + tx * 8;
        float4 s0 = make_float4(acc[i][0], acc[i][1], acc[i][2], acc[i][3]);
        float4 s1 = make_float4(acc[i][4], acc[i][5], acc[i][6], acc[i][7]);
        *(float4*)(cptr + 0) = s0;
        *(float4*)(cptr + 4) = s1;

        // Thread-local argmax over its 8 columns (lowest col wins on tie).
        float bestV = acc[i][0];
        int   bestJ = 0;
        #pragma unroll
        for (int j = 1; j < 8; j++) {
            if (acc[i][j] > bestV) { bestV = acc[i][j]; bestJ = j; }
        }
        int bestCol = colBase + tx * 8 + bestJ;
        unsigned long long packed =
            ((unsigned long long)f2ord(bestV) << 32) |
            (unsigned int)(K_CB - 1 - bestCol);   // complement: lower col wins ties

        // Reduce across the 16 tx-lanes that share this row (contiguous lanes).
        #pragma unroll
        for (int off = 8; off >= 1; off >>= 1) {
            unsigned long long o = __shfl_xor_sync(0xffffffffu, packed, off);
            if (o > packed) packed = o;
        }
        if (tx == 0) {
            atomicMax(&g_rowmax[row], packed);
        }
    }
}

__global__ void write_indices_kernel(float* __restrict__ out_idx) {
    int n = blockIdx.x * blockDim.x + threadIdx.x;
    if (n < N_ROWS) {
        unsigned int low = (unsigned int)(g_rowmax[n] & 0xffffffffull);
        out_idx[n] = (float)(K_CB - 1 - (int)low);
    }
}

extern "C" void kernel_launch(void* const* d_in, const int* in_sizes, int n_in,
                              void* d_out, int out_size) {
    const float* z  = (const float*)d_in[0];   // [32768, 512]
    const float* cb = (const float*)d_in[1];   // [4096, 512]
    float* out = (float*)d_out;

    float* logits  = out;                       // [N, K] flattened
    float* idx_out = out + (out_size - N_ROWS); // last N elements = indices

    init_rowmax_kernel<<<(N_ROWS + 255) / 256, 256>>>();

    dim3 grid(K_CB / 128, N_ROWS / 128);        // (32, 256)
    gemm_argmax_kernel<<<grid, 256>>>(z, cb, logits);

    write_indices_kernel<<<(N_ROWS + 255) / 256, 256>>>(idx_out);
}

// round 4
// speedup vs baseline: 5.8539x; 5.8539x over previous
#include <cuda_runtime.h>
#include <cuda_fp16.h>
#include <cstdint>

#define NROWS 32768
#define KCB   4096
#define DDIM  512

#define BM 128
#define BN 256
#define BK 64                 // halves per chunk = 128 bytes = SW128 row
#define NKCH (DDIM / BK)      // 8
#define NTILES (KCB / BN)     // 16
#define NTHREADS 512
#define MARGIN 1e-4f
#define BSCALE 4096.0f
#define INV_BSCALE (1.0f / 4096.0f)

#define A_STAGE_BYTES (BM * 128)            // 16384
#define B_STAGE_BYTES (BN * 128)            // 32768
#define STAGE_BYTES   (A_STAGE_BYTES + B_STAGE_BYTES)  // 49152
#define NSTAGE 3
#define SMEM_TOTAL (NSTAGE * STAGE_BYTES)   // 147456

// -------- device scratch (no allocs allowed) --------
__device__ __align__(16) __half gAh[(size_t)NROWS * DDIM];  // 33.5 MB
__device__ __align__(16) __half gBh[(size_t)KCB * DDIM];    // 4.2 MB, pre-scaled by 4096
__device__ unsigned long long g_tilemax[(size_t)NROWS * NTILES];  // 4 MB

// -------- helpers --------
__device__ __forceinline__ uint32_t smem_u32(const void* p) {
    uint32_t a;
    asm("{ .reg .u64 t; cvta.to.shared.u64 t, %1; cvt.u32.u64 %0, t; }" : "=r"(a) : "l"(p));
    return a;
}
__device__ __forceinline__ uint32_t sw128(uint32_t b) { return b ^ ((b >> 3) & 0x70); }

__device__ __forceinline__ unsigned int f2ord(float f) {
    unsigned int u = __float_as_uint(f);
    return (u & 0x80000000u) ? ~u : (u | 0x80000000u);
}
__device__ __forceinline__ float ord2f(unsigned int o) {
    unsigned int u = (o & 0x80000000u) ? (o & 0x7FFFFFFFu) : ~o;
    return __uint_as_float(u);
}
__device__ __forceinline__ void cp_async16(uint32_t s, const void* g) {
    asm volatile("cp.async.cg.shared.global [%0], [%1], 16;"
                 :: "r"(s), "l"(__cvta_generic_to_global(g)));
}
__device__ __forceinline__ void cp_commit() { asm volatile("cp.async.commit_group;" ::: "memory"); }
template <int N> __device__ __forceinline__ void cp_wait() {
    asm volatile("cp.async.wait_group %0;" :: "n"(N) : "memory");
}
__device__ __forceinline__ void ldm_x4(uint32_t& r0, uint32_t& r1, uint32_t& r2, uint32_t& r3,
                                       uint32_t addr) {
    asm volatile("ldmatrix.sync.aligned.m8n8.x4.shared.b16 {%0,%1,%2,%3}, [%4];"
                 : "=r"(r0), "=r"(r1), "=r"(r2), "=r"(r3) : "r"(addr));
}
__device__ __forceinline__ void mma_f16(float* c, uint32_t a0, uint32_t a1, uint32_t a2,
                                        uint32_t a3, uint32_t b0, uint32_t b1) {
    asm volatile(
        "mma.sync.aligned.m16n8k16.row.col.f32.f16.f16.f32 "
        "{%0,%1,%2,%3}, {%4,%5,%6,%7}, {%8,%9}, {%0,%1,%2,%3};"
        : "+f"(c[0]), "+f"(c[1]), "+f"(c[2]), "+f"(c[3])
        : "r"(a0), "r"(a1), "r"(a2), "r"(a3), "r"(b0), "r"(b1));
}
__device__ __forceinline__ uint32_t h2u(__half2 h) { return *reinterpret_cast<uint32_t*>(&h); }

// -------- kernels --------
#define A8 ((size_t)NROWS * DDIM / 8)  // 2097152
#define B8 ((size_t)KCB * DDIM / 8)    // 262144

__global__ __launch_bounds__(512)
void convert_kernel(const float* __restrict__ A, const float* __restrict__ B) {
    size_t id = (size_t)blockIdx.x * blockDim.x + threadIdx.x;
    if (id < A8) {
        float4 f0 = ((const float4*)A)[2 * id];
        float4 f1 = ((const float4*)A)[2 * id + 1];
        uint4 o;
        o.x = h2u(__float22half2_rn(make_float2(f0.x, f0.y)));
        o.y = h2u(__float22half2_rn(make_float2(f0.z, f0.w)));
        o.z = h2u(__float22half2_rn(make_float2(f1.x, f1.y)));
        o.w = h2u(__float22half2_rn(make_float2(f1.z, f1.w)));
        ((uint4*)gAh)[id] = o;
    } else if (id < A8 + B8) {
        size_t j = id - A8;
        float4 f0 = ((const float4*)B)[2 * j];
        float4 f1 = ((const float4*)B)[2 * j + 1];
        uint4 o;
        o.x = h2u(__float22half2_rn(make_float2(f0.x * BSCALE, f0.y * BSCALE)));
        o.y = h2u(__float22half2_rn(make_float2(f0.z * BSCALE, f0.w * BSCALE)));
        o.z = h2u(__float22half2_rn(make_float2(f1.x * BSCALE, f1.y * BSCALE)));
        o.w = h2u(__float22half2_rn(make_float2(f1.z * BSCALE, f1.w * BSCALE)));
        ((uint4*)gBh)[j] = o;
    }
}

__global__ void init_tilemax_kernel() {
    size_t i = (size_t)blockIdx.x * blockDim.x + threadIdx.x;
    if (i < (size_t)NROWS * NTILES) g_tilemax[i] = 0ull;
}

__global__ __launch_bounds__(NTHREADS, 1)
void gemm_f16_kernel(float* __restrict__ C) {
    extern __shared__ char smem[];
    const uint32_t sbase = smem_u32(smem);
    const int tid = threadIdx.x;
    const int wid = tid >> 5;
    const int lane = tid & 31;
    const int warpM = wid >> 3;   // 0..1
    const int warpN = wid & 7;    // 0..7

    const int rowBase = blockIdx.y * BM;
    const int colBase = blockIdx.x * BN;

    // staging addresses (hoisted)
    int aRow[2], aSw[2], bRow[4], bSw[4];
#pragma unroll
    for (int i = 0; i < 2; i++) {
        int idx = tid + i * NTHREADS;           // 0..1023
        aRow[i] = idx >> 3;
        aSw[i] = sw128((idx >> 3) * 128 + (idx & 7) * 16);
    }
#pragma unroll
    for (int i = 0; i < 4; i++) {
        int idx = tid + i * NTHREADS;           // 0..2047
        bRow[i] = idx >> 3;
        bSw[i] = sw128((idx >> 3) * 128 + (idx & 7) * 16);
    }
    int aC8[2], bC8[4];
#pragma unroll
    for (int i = 0; i < 2; i++) aC8[i] = (tid + i * NTHREADS) & 7;
#pragma unroll
    for (int i = 0; i < 4; i++) bC8[i] = (tid + i * NTHREADS) & 7;

#define STAGE(ks_, st_)                                                                  \
    do {                                                                                 \
        uint32_t base_ = sbase + (st_) * STAGE_BYTES;                                    \
        _Pragma("unroll")                                                                \
        for (int i_ = 0; i_ < 2; i_++)                                                   \
            cp_async16(base_ + aSw[i_],                                                  \
                       gAh + (size_t)(rowBase + aRow[i_]) * DDIM + (ks_) * BK + aC8[i_] * 8); \
        _Pragma("unroll")                                                                \
        for (int i_ = 0; i_ < 4; i_++)                                                   \
            cp_async16(base_ + A_STAGE_BYTES + bSw[i_],                                  \
                       gBh + (size_t)(colBase + bRow[i_]) * DDIM + (ks_) * BK + bC8[i_] * 8); \
        cp_commit();                                                                     \
    } while (0)

    // fragment addressing (byte math within 128B rows, SW128)
    const int aRowOff = (lane & 7) | (((lane >> 3) & 1) << 3);
    const int aColSel = (lane >> 4) << 4;
    const int bRowOff = (lane & 7) | (((lane >> 4) & 1) << 3);
    const int bColSel = ((lane >> 3) & 1) << 4;

    uint32_t aBase[4], aXor[4], bBase[2], bXor[2];
#pragma unroll
    for (int mi = 0; mi < 4; mi++) {
        int r = warpM * 64 + mi * 16 + aRowOff;
        aBase[mi] = r * 128;
        aXor[mi] = (r & 7) << 4;
    }
#pragma unroll
    for (int p = 0; p < 2; p++) {
        int r = warpN * 32 + p * 16 + bRowOff;
        bBase[p] = A_STAGE_BYTES + r * 128;
        bXor[p] = (r & 7) << 4;
    }

    float acc[4][4][4];
#pragma unroll
    for (int mi = 0; mi < 4; mi++)
#pragma unroll
        for (int ni = 0; ni < 4; ni++)
#pragma unroll
            for (int r = 0; r < 4; r++) acc[mi][ni][r] = 0.0f;

    STAGE(0, 0);
    STAGE(1, 1);

#pragma unroll
    for (int ks = 0; ks < NKCH; ks++) {
        if (ks < NKCH - 1) cp_wait<1>(); else cp_wait<0>();
        __syncthreads();
        if (ks + 2 < NKCH) STAGE(ks + 2, (ks + 2) % NSTAGE);

        const uint32_t buf = sbase + (ks % NSTAGE) * STAGE_BYTES;
#pragma unroll
        for (int kk = 0; kk < 4; kk++) {
            uint32_t a[4][4], b[2][4];
#pragma unroll
            for (int mi = 0; mi < 4; mi++)
                ldm_x4(a[mi][0], a[mi][1], a[mi][2], a[mi][3],
                       buf + aBase[mi] + (((uint32_t)(kk * 32 + aColSel)) ^ aXor[mi]));
#pragma unroll
            for (int p = 0; p < 2; p++)
                ldm_x4(b[p][0], b[p][1], b[p][2], b[p][3],
                       buf + bBase[p] + (((uint32_t)(kk * 32 + bColSel)) ^ bXor[p]));
#pragma unroll
            for (int mi = 0; mi < 4; mi++)
#pragma unroll
                for (int ni = 0; ni < 4; ni++)
                    mma_f16(acc[mi][ni], a[mi][0], a[mi][1], a[mi][2], a[mi][3],
                            b[ni >> 1][2 * (ni & 1)], b[ni >> 1][2 * (ni & 1) + 1]);
        }
    }
#undef STAGE

    // ---- epilogue: descale, store logits, packed per-(row,tile) argmax ----
#pragma unroll
    for (int mi = 0; mi < 4; mi++) {
        const int rbase = rowBase + warpM * 64 + mi * 16 + (lane >> 2);
#pragma unroll
        for (int h = 0; h < 2; h++) {
            const int row = rbase + h * 8;
            float* cr = C + (size_t)row * KCB + colBase + warpN * 32 + (lane & 3) * 2;
            unsigned long long packed = 0ull;
#pragma unroll
            for (int ni = 0; ni < 4; ni++) {
                float v0 = acc[mi][ni][h * 2] * INV_BSCALE;
                float v1 = acc[mi][ni][h * 2 + 1] * INV_BSCALE;
                *(float2*)(cr + ni * 8) = make_float2(v0, v1);
                int col0 = colBase + warpN * 32 + ni * 8 + (lane & 3) * 2;
                unsigned long long p0 =
                    ((unsigned long long)f2ord(v0) << 32) | (unsigned int)(KCB - 1 - col0);
                unsigned long long p1 =
                    ((unsigned long long)f2ord(v1) << 32) | (unsigned int)(KCB - 2 - col0);
                if (p0 > packed) packed = p0;
                if (p1 > packed) packed = p1;
            }
#pragma unroll
            for (int off = 1; off <= 2; off <<= 1) {
                unsigned long long o = __shfl_xor_sync(0xffffffffu, packed, off);
                if (o > packed) packed = o;
            }
            if ((lane & 3) == 0)
                atomicMax(&g_tilemax[(size_t)row * NTILES + blockIdx.x], packed);
        }
    }
}

// one warp per row: approx global max from tilemax, margin scan, exact fp32 rescore
__global__ __launch_bounds__(256)
void refine_kernel(const float* __restrict__ A, const float* __restrict__ B,
                   const float* __restrict__ C, float* __restrict__ idx_out) {
    const int n = (blockIdx.x * blockDim.x + threadIdx.x) >> 5;
    const int lane = threadIdx.x & 31;
    if (n >= NROWS) return;

    unsigned long long tm = (lane < NTILES) ? g_tilemax[(size_t)n * NTILES + lane] : 0ull;
    unsigned long long mx = tm;
#pragma unroll
    for (int o = 16; o >= 1; o >>= 1) {
        unsigned long long t = __shfl_xor_sync(0xffffffffu, mx, o);
        if (t > mx) mx = t;
    }
    const float thr = ord2f((unsigned int)(mx >> 32)) - MARGIN;

    float bestV = -3.4e38f;
    int bestC = KCB;
    const float* zrow = A + (size_t)n * DDIM;

    for (int t = 0; t < NTILES; t++) {
        unsigned long long tmt = __shfl_sync(0xffffffffu, tm, t);
        if (ord2f((unsigned int)(tmt >> 32)) < thr) continue;
#pragma unroll 1
        for (int g = 0; g < BN / 32; g++) {
            int col = t * BN + g * 32 + lane;
            float v = C[(size_t)n * KCB + col];
            unsigned mask = __ballot_sync(0xffffffffu, v >= thr);
            while (mask) {
                int src = __ffs(mask) - 1;
                mask &= mask - 1;
                int cc = t * BN + g * 32 + src;
                const float* brow = B + (size_t)cc * DDIM;
                float acc = 0.0f;
#pragma unroll
                for (int j = 0; j < 16; j++)
                    acc = fmaf(zrow[lane + 32 * j], brow[lane + 32 * j], acc);
#pragma unroll
                for (int o = 16; o >= 1; o >>= 1) acc += __shfl_xor_sync(0xffffffffu, acc, o);
                if (acc > bestV || (acc == bestV && cc < bestC)) { bestV = acc; bestC = cc; }
            }
        }
    }
    if (lane == 0) idx_out[n] = (float)bestC;
}

// -------- launch --------
extern "C" void kernel_launch(void* const* d_in, const int* in_sizes, int n_in,
                              void* d_out, int out_size) {
    const float* z  = (const float*)d_in[0];   // [32768, 512]
    const float* cb = (const float*)d_in[1];   // [4096, 512]
    float* out = (float*)d_out;
    float* logits = out;
    float* idx_out = out + ((size_t)out_size - NROWS);

    cudaFuncSetAttribute(gemm_f16_kernel, cudaFuncAttributeMaxDynamicSharedMemorySize,
                         SMEM_TOTAL);

    size_t convN = A8 + B8;
    convert_kernel<<<(unsigned)((convN + 511) / 512), 512>>>(z, cb);
    init_tilemax_kernel<<<(NROWS * NTILES + 511) / 512, 512>>>();

    dim3 grid(KCB / BN, NROWS / BM);  // (16, 256)
    gemm_f16_kernel<<<grid, NTHREADS, SMEM_TOTAL>>>(logits);

    refine_kernel<<<NROWS / 8, 256>>>(z, cb, logits, idx_out);
}

// round 5
// speedup vs baseline: 6.2411x; 1.0661x over previous
#include <cuda_runtime.h>
#include <cuda_fp16.h>
#include <cstdint>

#define NROWS 32768
#define KCB   4096
#define DDIM  512

#define BM 128
#define BN 256
#define NCT 4                  // col tiles per CTA
#define NKCH 8                 // k-chunks (64 halves each)
#define TCH (NCT * NKCH)       // 32 chunk iterations
#define NTHREADS 512
#define MARGIN 1e-4f
#define BSCALE 4096.0f
#define INV_BSCALE (1.0f / 4096.0f)
#define NGROUPS (KCB / 32)     // 128

#define A_BYTES (BM * DDIM * 2)          // 131072 (A resident, 8 chunk blocks of 16KB)
#define B_STAGE (BN * 128)               // 32768
#define SMEM_TOTAL (A_BYTES + 3 * B_STAGE)  // 229376

// -------- device scratch --------
__device__ __align__(16) __half gAh[(size_t)NROWS * DDIM];
__device__ __align__(16) __half gBh[(size_t)KCB * DDIM];          // pre-scaled by 4096
__device__ unsigned long long g_groupmax[(size_t)NROWS * NGROUPS]; // 33.5 MB

// -------- helpers --------
__device__ __forceinline__ uint32_t smem_u32(const void* p) {
    uint32_t a;
    asm("{ .reg .u64 t; cvta.to.shared.u64 t, %1; cvt.u32.u64 %0, t; }" : "=r"(a) : "l"(p));
    return a;
}
__device__ __forceinline__ uint32_t sw128(uint32_t b) { return b ^ ((b >> 3) & 0x70); }
__device__ __forceinline__ unsigned int f2ord(float f) {
    unsigned int u = __float_as_uint(f);
    return (u & 0x80000000u) ? ~u : (u | 0x80000000u);
}
__device__ __forceinline__ float ord2f(unsigned int o) {
    unsigned int u = (o & 0x80000000u) ? (o & 0x7FFFFFFFu) : ~o;
    return __uint_as_float(u);
}
__device__ __forceinline__ void cp_async16(uint32_t s, const void* g) {
    asm volatile("cp.async.cg.shared.global [%0], [%1], 16;"
                 :: "r"(s), "l"(__cvta_generic_to_global(g)));
}
__device__ __forceinline__ void cp_commit() { asm volatile("cp.async.commit_group;" ::: "memory"); }
template <int N> __device__ __forceinline__ void cp_wait() {
    asm volatile("cp.async.wait_group %0;" :: "n"(N) : "memory");
}
__device__ __forceinline__ void ldm_x4(uint32_t& r0, uint32_t& r1, uint32_t& r2, uint32_t& r3,
                                       uint32_t addr) {
    asm volatile("ldmatrix.sync.aligned.m8n8.x4.shared.b16 {%0,%1,%2,%3}, [%4];"
                 : "=r"(r0), "=r"(r1), "=r"(r2), "=r"(r3) : "r"(addr));
}
__device__ __forceinline__ void mma_f16(float* c, uint32_t a0, uint32_t a1, uint32_t a2,
                                        uint32_t a3, uint32_t b0, uint32_t b1) {
    asm volatile(
        "mma.sync.aligned.m16n8k16.row.col.f32.f16.f16.f32 "
        "{%0,%1,%2,%3}, {%4,%5,%6,%7}, {%8,%9}, {%0,%1,%2,%3};"
        : "+f"(c[0]), "+f"(c[1]), "+f"(c[2]), "+f"(c[3])
        : "r"(a0), "r"(a1), "r"(a2), "r"(a3), "r"(b0), "r"(b1));
}
__device__ __forceinline__ uint32_t h2u(__half2 h) { return *reinterpret_cast<uint32_t*>(&h); }

// -------- convert --------
#define A8 ((size_t)NROWS * DDIM / 8)
#define B8 ((size_t)KCB * DDIM / 8)

__global__ __launch_bounds__(512)
void convert_kernel(const float* __restrict__ A, const float* __restrict__ B) {
    size_t id = (size_t)blockIdx.x * blockDim.x + threadIdx.x;
    if (id < A8) {
        float4 f0 = ((const float4*)A)[2 * id];
        float4 f1 = ((const float4*)A)[2 * id + 1];
        uint4 o;
        o.x = h2u(__float22half2_rn(make_float2(f0.x, f0.y)));
        o.y = h2u(__float22half2_rn(make_float2(f0.z, f0.w)));
        o.z = h2u(__float22half2_rn(make_float2(f1.x, f1.y)));
        o.w = h2u(__float22half2_rn(make_float2(f1.z, f1.w)));
        ((uint4*)gAh)[id] = o;
    } else if (id < A8 + B8) {
        size_t j = id - A8;
        float4 f0 = ((const float4*)B)[2 * j];
        float4 f1 = ((const float4*)B)[2 * j + 1];
        uint4 o;
        o.x = h2u(__float22half2_rn(make_float2(f0.x * BSCALE, f0.y * BSCALE)));
        o.y = h2u(__float22half2_rn(make_float2(f0.z * BSCALE, f0.w * BSCALE)));
        o.z = h2u(__float22half2_rn(make_float2(f1.x * BSCALE, f1.y * BSCALE)));
        o.w = h2u(__float22half2_rn(make_float2(f1.z * BSCALE, f1.w * BSCALE)));
        ((uint4*)gBh)[j] = o;
    }
}

// -------- GEMM: A-resident, 4 col tiles per CTA --------
__global__ __launch_bounds__(NTHREADS, 1)
void gemm_f16_kernel(float* __restrict__ C) {
    extern __shared__ char smem[];
    const uint32_t sbase = smem_u32(smem);
    const int tid = threadIdx.x;
    const int wid = tid >> 5;
    const int lane = tid & 31;
    const int warpM = wid >> 3;   // 0..1
    const int warpN = wid & 7;    // 0..7

    const int rowBase = blockIdx.y * BM;
    const int ctaCol = blockIdx.x * (BN * NCT);   // 1024-wide stripe

    // ---- stage entire A stripe (8 chunk blocks of 16KB) ----
#pragma unroll
    for (int i = 0; i < 16; i++) {
        int idx = tid + i * NTHREADS;      // 0..8191
        int ks = idx >> 10;
        int r = (idx >> 3) & 127;
        int c = idx & 7;
        cp_async16(sbase + ks * 16384 + sw128(r * 128 + c * 16),
                   gAh + (size_t)(rowBase + r) * DDIM + ks * 64 + c * 8);
    }
    cp_commit();

    // B stage: global chunk index gc (0..31): tile = gc>>3, ks = gc&7
#define BSTAGE(gc_, slot_)                                                               \
    do {                                                                                 \
        uint32_t bb_ = sbase + A_BYTES + (slot_) * B_STAGE;                              \
        int tcol_ = ctaCol + ((gc_) >> 3) * BN;                                          \
        int kso_ = ((gc_) & 7) * 64;                                                     \
        _Pragma("unroll")                                                                \
        for (int i_ = 0; i_ < 4; i_++) {                                                 \
            int idx_ = tid + i_ * NTHREADS;  /* 0..2047 */                               \
            int r_ = idx_ >> 3, c_ = idx_ & 7;                                           \
            cp_async16(bb_ + sw128(r_ * 128 + c_ * 16),                                  \
                       gBh + (size_t)(tcol_ + r_) * DDIM + kso_ + c_ * 8);               \
        }                                                                                \
        cp_commit();                                                                     \
    } while (0)

    BSTAGE(0, 0);
    BSTAGE(1, 1);

    // ---- fragment addressing ----
    const int aRowOff = (lane & 7) | (((lane >> 3) & 1) << 3);
    const int aColSel = (lane >> 4) << 4;
    const int bRowOff = (lane & 7) | (((lane >> 4) & 1) << 3);
    const int bColSel = ((lane >> 3) & 1) << 4;

    uint32_t aBase[4], aXor[4], bOff[2], bXor[2];
#pragma unroll
    for (int mi = 0; mi < 4; mi++) {
        int r = warpM * 64 + mi * 16 + aRowOff;
        aBase[mi] = r * 128;
        aXor[mi] = (r & 7) << 4;
    }
#pragma unroll
    for (int p = 0; p < 2; p++) {
        int r = warpN * 32 + p * 16 + bRowOff;
        bOff[p] = r * 128;
        bXor[p] = (r & 7) << 4;
    }

    float acc[4][4][4];

#pragma unroll 1
    for (int gc = 0; gc < TCH; gc++) {
        const int tile = gc >> 3;
        const int ks = gc & 7;
        const int slot = gc % 3;

        if (gc == TCH - 1) cp_wait<0>(); else cp_wait<1>();
        __syncthreads();
        if (gc + 2 < TCH) BSTAGE(gc + 2, (gc + 2) % 3);

        if (ks == 0) {
#pragma unroll
            for (int mi = 0; mi < 4; mi++)
#pragma unroll
                for (int ni = 0; ni < 4; ni++)
#pragma unroll
                    for (int r = 0; r < 4; r++) acc[mi][ni][r] = 0.0f;
        }

        const uint32_t aBuf = sbase + ks * 16384;
        const uint32_t bBuf = sbase + A_BYTES + slot * B_STAGE;
#pragma unroll
        for (int kk = 0; kk < 4; kk++) {
            uint32_t a[4][4], b[2][4];
#pragma unroll
            for (int mi = 0; mi < 4; mi++)
                ldm_x4(a[mi][0], a[mi][1], a[mi][2], a[mi][3],
                       aBuf + aBase[mi] + (((uint32_t)(kk * 32 + aColSel)) ^ aXor[mi]));
#pragma unroll
            for (int p = 0; p < 2; p++)
                ldm_x4(b[p][0], b[p][1], b[p][2], b[p][3],
                       bBuf + bOff[p] + (((uint32_t)(kk * 32 + bColSel)) ^ bXor[p]));
#pragma unroll
            for (int mi = 0; mi < 4; mi++)
#pragma unroll
                for (int ni = 0; ni < 4; ni++)
                    mma_f16(acc[mi][ni], a[mi][0], a[mi][1], a[mi][2], a[mi][3],
                            b[ni >> 1][2 * (ni & 1)], b[ni >> 1][2 * (ni & 1) + 1]);
        }

        // ---- per-tile epilogue ----
        if (ks == 7) {
            const int colT = ctaCol + tile * BN;
#pragma unroll
            for (int mi = 0; mi < 4; mi++) {
                const int rbase = rowBase + warpM * 64 + mi * 16 + (lane >> 2);
#pragma unroll
                for (int h = 0; h < 2; h++) {
                    const int row = rbase + h * 8;
                    float* cr = C + (size_t)row * KCB + colT + warpN * 32 + (lane & 3) * 2;
                    unsigned long long packed = 0ull;
#pragma unroll
                    for (int ni = 0; ni < 4; ni++) {
                        float v0 = acc[mi][ni][h * 2] * INV_BSCALE;
                        float v1 = acc[mi][ni][h * 2 + 1] * INV_BSCALE;
                        *(float2*)(cr + ni * 8) = make_float2(v0, v1);
                        int col0 = colT + warpN * 32 + ni * 8 + (lane & 3) * 2;
                        unsigned long long p0 =
                            ((unsigned long long)f2ord(v0) << 32) | (unsigned int)(KCB - 1 - col0);
                        unsigned long long p1 =
                            ((unsigned long long)f2ord(v1) << 32) | (unsigned int)(KCB - 2 - col0);
                        if (p0 > packed) packed = p0;
                        if (p1 > packed) packed = p1;
                    }
#pragma unroll
                    for (int off = 1; off <= 2; off <<= 1) {
                        unsigned long long o = __shfl_xor_sync(0xffffffffu, packed, off);
                        if (o > packed) packed = o;
                    }
                    if ((lane & 3) == 0)
                        g_groupmax[(size_t)row * NGROUPS + (colT >> 5) + warpN] = packed;
                }
            }
        }
    }
#undef BSTAGE
}

// -------- refine: warp/row, groupmax prune, skip rescore if single candidate --------
__global__ __launch_bounds__(256)
void refine_kernel(const float* __restrict__ A, const float* __restrict__ B,
                   const float* __restrict__ C, float* __restrict__ idx_out) {
    const int n = (blockIdx.x * blockDim.x + threadIdx.x) >> 5;
    const int lane = threadIdx.x & 31;
    if (n >= NROWS) return;

    const unsigned long long* gm = g_groupmax + (size_t)n * NGROUPS;
    unsigned long long pm[4];
#pragma unroll
    for (int j = 0; j < 4; j++) pm[j] = gm[lane + 32 * j];

    unsigned long long mx = pm[0];
#pragma unroll
    for (int j = 1; j < 4; j++) if (pm[j] > mx) mx = pm[j];
#pragma unroll
    for (int o = 16; o >= 1; o >>= 1) {
        unsigned long long t = __shfl_xor_sync(0xffffffffu, mx, o);
        if (t > mx) mx = t;
    }
    const float thr = ord2f((unsigned int)(mx >> 32)) - MARGIN;
    const float* crow = C + (size_t)n * KCB;

    // pass 1: count candidates
    int totalc = 0;
#pragma unroll
    for (int j = 0; j < 4; j++) {
        unsigned gmask = __ballot_sync(0xffffffffu, ord2f((unsigned int)(pm[j] >> 32)) >= thr);
        while (gmask) {
            int src = __ffs(gmask) - 1;
            gmask &= gmask - 1;
            int g = 32 * j + src;
            float v = crow[g * 32 + lane];
            totalc += __popc(__ballot_sync(0xffffffffu, v >= thr));
        }
    }

    int bestC;
    if (totalc <= 1) {
        bestC = KCB - 1 - (int)(unsigned int)(mx & 0xffffffffull);
    } else {
        float bestV = -3.4e38f;
        bestC = KCB;
        const float* zrow = A + (size_t)n * DDIM;
#pragma unroll
        for (int j = 0; j < 4; j++) {
            unsigned gmask = __ballot_sync(0xffffffffu, ord2f((unsigned int)(pm[j] >> 32)) >= thr);
            while (gmask) {
                int src = __ffs(gmask) - 1;
                gmask &= gmask - 1;
                int g = 32 * j + src;
                float v = crow[g * 32 + lane];
                unsigned cmask = __ballot_sync(0xffffffffu, v >= thr);
                while (cmask) {
                    int cs = __ffs(cmask) - 1;
                    cmask &= cmask - 1;
                    int cc = g * 32 + cs;
                    const float* brow = B + (size_t)cc * DDIM;
                    float acc = 0.0f;
#pragma unroll
                    for (int q = 0; q < 16; q++)
                        acc = fmaf(zrow[lane + 32 * q], brow[lane + 32 * q], acc);
#pragma unroll
                    for (int o = 16; o >= 1; o >>= 1)
                        acc += __shfl_xor_sync(0xffffffffu, acc, o);
                    if (acc > bestV || (acc == bestV && cc < bestC)) { bestV = acc; bestC = cc; }
                }
            }
        }
    }
    if (lane == 0) idx_out[n] = (float)bestC;
}

// -------- launch --------
extern "C" void kernel_launch(void* const* d_in, const int* in_sizes, int n_in,
                              void* d_out, int out_size) {
    const float* z  = (const float*)d_in[0];   // [32768, 512]
    const float* cb = (const float*)d_in[1];   // [4096, 512]
    float* out = (float*)d_out;
    float* logits = out;
    float* idx_out = out + ((size_t)out_size - NROWS);

    cudaFuncSetAttribute(gemm_f16_kernel, cudaFuncAttributeMaxDynamicSharedMemorySize,
                         SMEM_TOTAL);

    size_t convN = A8 + B8;
    convert_kernel<<<(unsigned)((convN + 511) / 512), 512>>>(z, cb);

    dim3 grid(KCB / (BN * NCT), NROWS / BM);  // (4, 256)
    gemm_f16_kernel<<<grid, NTHREADS, SMEM_TOTAL>>>(logits);

    refine_kernel<<<NROWS / 8, 256>>>(z, cb, logits, idx_out);
}

// round 8
// speedup vs baseline: 6.9308x; 1.1105x over previous
#include <cuda_runtime.h>
#include <cuda_fp16.h>
#include <cstdint>

#define NROWS 32768
#define KCB   4096
#define DDIM  512

#define BM 128
#define BN 128
#define BK 64                 // halves per chunk = 128 bytes = SW128 row
#define NKCH (DDIM / BK)      // 8
#define NTHREADS 256
#define MARGIN 1e-4f
#define BSCALE 4096.0f
#define INV_BSCALE (1.0f / 4096.0f)
#define NGROUPS (KCB / 32)    // 128

#define A_STAGE (BM * 128)    // 16384
#define B_STAGE (BN * 128)    // 16384
#define STAGE_BYTES (A_STAGE + B_STAGE)   // 32768
#define NSTAGE 3
#define SMEM_TOTAL (NSTAGE * STAGE_BYTES) // 98304

// -------- device scratch --------
__device__ __align__(16) __half gAh[(size_t)NROWS * DDIM];
__device__ __align__(16) __half gBh[(size_t)KCB * DDIM];           // pre-scaled by 4096
__device__ unsigned long long g_groupmax[(size_t)NROWS * NGROUPS]; // 33.5 MB

// -------- helpers --------
__device__ __forceinline__ uint32_t smem_u32(const void* p) {
    uint32_t a;
    asm("{ .reg .u64 t; cvta.to.shared.u64 t, %1; cvt.u32.u64 %0, t; }" : "=r"(a) : "l"(p));
    return a;
}
__device__ __forceinline__ uint32_t sw128(uint32_t b) { return b ^ ((b >> 3) & 0x70); }
__device__ __forceinline__ unsigned int f2ord(float f) {
    unsigned int u = __float_as_uint(f);
    return (u & 0x80000000u) ? ~u : (u | 0x80000000u);
}
__device__ __forceinline__ float ord2f(unsigned int o) {
    unsigned int u = (o & 0x80000000u) ? (o & 0x7FFFFFFFu) : ~o;
    return __uint_as_float(u);
}
__device__ __forceinline__ void cp_async16(uint32_t s, const void* g) {
    asm volatile("cp.async.cg.shared.global [%0], [%1], 16;"
                 :: "r"(s), "l"(__cvta_generic_to_global(g)));
}
__device__ __forceinline__ void cp_commit() { asm volatile("cp.async.commit_group;" ::: "memory"); }
template <int N> __device__ __forceinline__ void cp_wait() {
    asm volatile("cp.async.wait_group %0;" :: "n"(N) : "memory");
}
__device__ __forceinline__ void ldm_x4(uint32_t& r0, uint32_t& r1, uint32_t& r2, uint32_t& r3,
                                       uint32_t addr) {
    asm volatile("ldmatrix.sync.aligned.m8n8.x4.shared.b16 {%0,%1,%2,%3}, [%4];"
                 : "=r"(r0), "=r"(r1), "=r"(r2), "=r"(r3) : "r"(addr));
}
__device__ __forceinline__ void mma_f16(float* c, uint32_t a0, uint32_t a1, uint32_t a2,
                                        uint32_t a3, uint32_t b0, uint32_t b1) {
    asm volatile(
        "mma.sync.aligned.m16n8k16.row.col.f32.f16.f16.f32 "
        "{%0,%1,%2,%3}, {%4,%5,%6,%7}, {%8,%9}, {%0,%1,%2,%3};"
        : "+f"(c[0]), "+f"(c[1]), "+f"(c[2]), "+f"(c[3])
        : "r"(a0), "r"(a1), "r"(a2), "r"(a3), "r"(b0), "r"(b1));
}
__device__ __forceinline__ uint32_t h2u(__half2 h) { return *reinterpret_cast<uint32_t*>(&h); }

// -------- convert --------
#define A8 ((size_t)NROWS * DDIM / 8)
#define B8 ((size_t)KCB * DDIM / 8)

__global__ __launch_bounds__(512)
void convert_kernel(const float* __restrict__ A, const float* __restrict__ B) {
    size_t id = (size_t)blockIdx.x * blockDim.x + threadIdx.x;
    if (id < A8) {
        float4 f0 = ((const float4*)A)[2 * id];
        float4 f1 = ((const float4*)A)[2 * id + 1];
        uint4 o;
        o.x = h2u(__float22half2_rn(make_float2(f0.x, f0.y)));
        o.y = h2u(__float22half2_rn(make_float2(f0.z, f0.w)));
        o.z = h2u(__float22half2_rn(make_float2(f1.x, f1.y)));
        o.w = h2u(__float22half2_rn(make_float2(f1.z, f1.w)));
        ((uint4*)gAh)[id] = o;
    } else if (id < A8 + B8) {
        size_t j = id - A8;
        float4 f0 = ((const float4*)B)[2 * j];
        float4 f1 = ((const float4*)B)[2 * j + 1];
        uint4 o;
        o.x = h2u(__float22half2_rn(make_float2(f0.x * BSCALE, f0.y * BSCALE)));
        o.y = h2u(__float22half2_rn(make_float2(f0.z * BSCALE, f0.w * BSCALE)));
        o.z = h2u(__float22half2_rn(make_float2(f1.x * BSCALE, f1.y * BSCALE)));
        o.w = h2u(__float22half2_rn(make_float2(f1.z * BSCALE, f1.w * BSCALE)));
        ((uint4*)gBh)[j] = o;
    }
}

// -------- GEMM: 128x128 tile, 256 threads, 2 CTAs/SM --------
__global__ __launch_bounds__(NTHREADS, 2)
void gemm_f16_kernel(float* __restrict__ C) {
    extern __shared__ char smem[];
    const uint32_t sbase = smem_u32(smem);
    const int tid = threadIdx.x;
    const int wid = tid >> 5;
    const int lane = tid & 31;
    const int warpM = wid >> 2;   // 0..1
    const int warpN = wid & 3;    // 0..3

    const int rowBase = blockIdx.y * BM;
    const int colBase = blockIdx.x * BN;

    // staging addresses (hoisted): 4 A-transfers + 4 B-transfers per thread
    int rIdx[4];
    uint32_t swOff[4];
    int c8[4];
#pragma unroll
    for (int i = 0; i < 4; i++) {
        int idx = tid + i * NTHREADS;           // 0..1023
        rIdx[i] = idx >> 3;
        swOff[i] = sw128((idx >> 3) * 128 + (idx & 7) * 16);
        c8[i] = idx & 7;
    }

#define STAGE(ks_, st_)                                                                   \
    do {                                                                                  \
        uint32_t base_ = sbase + (st_) * STAGE_BYTES;                                     \
        _Pragma("unroll")                                                                 \
        for (int i_ = 0; i_ < 4; i_++)                                                    \
            cp_async16(base_ + swOff[i_],                                                 \
                       gAh + (size_t)(rowBase + rIdx[i_]) * DDIM + (ks_) * BK + c8[i_] * 8); \
        _Pragma("unroll")                                                                 \
        for (int i_ = 0; i_ < 4; i_++)                                                    \
            cp_async16(base_ + A_STAGE + swOff[i_],                                       \
                       gBh + (size_t)(colBase + rIdx[i_]) * DDIM + (ks_) * BK + c8[i_] * 8); \
        cp_commit();                                                                      \
    } while (0)

    // fragment addressing (byte math within 128B SW128 rows)
    const int aRowOff = (lane & 7) | (((lane >> 3) & 1) << 3);
    const int aColSel = (lane >> 4) << 4;
    const int bRowOff = (lane & 7) | (((lane >> 4) & 1) << 3);
    const int bColSel = ((lane >> 3) & 1) << 4;

    uint32_t aBase[4], aXor[4], bBase[2], bXor[2];
#pragma unroll
    for (int mi = 0; mi < 4; mi++) {
        int r = warpM * 64 + mi * 16 + aRowOff;
        aBase[mi] = r * 128;
        aXor[mi] = (r & 7) << 4;
    }
#pragma unroll
    for (int p = 0; p < 2; p++) {
        int r = warpN * 32 + p * 16 + bRowOff;
        bBase[p] = A_STAGE + r * 128;
        bXor[p] = (r & 7) << 4;
    }

    float acc[4][4][4];
#pragma unroll
    for (int mi = 0; mi < 4; mi++)
#pragma unroll
        for (int ni = 0; ni < 4; ni++)
#pragma unroll
            for (int r = 0; r < 4; r++) acc[mi][ni][r] = 0.0f;

    STAGE(0, 0);
    STAGE(1, 1);

#pragma unroll
    for (int ks = 0; ks < NKCH; ks++) {
        if (ks < NKCH - 1) cp_wait<1>(); else cp_wait<0>();
        __syncthreads();
        if (ks + 2 < NKCH) STAGE(ks + 2, (ks + 2) % NSTAGE);

        const uint32_t buf = sbase + (ks % NSTAGE) * STAGE_BYTES;
#pragma unroll
        for (int kk = 0; kk < 4; kk++) {
            uint32_t a[4][4], b[2][4];
#pragma unroll
            for (int mi = 0; mi < 4; mi++)
                ldm_x4(a[mi][0], a[mi][1], a[mi][2], a[mi][3],
                       buf + aBase[mi] + (((uint32_t)(kk * 32 + aColSel)) ^ aXor[mi]));
#pragma unroll
            for (int p = 0; p < 2; p++)
                ldm_x4(b[p][0], b[p][1], b[p][2], b[p][3],
                       buf + bBase[p] + (((uint32_t)(kk * 32 + bColSel)) ^ bXor[p]));
#pragma unroll
            for (int mi = 0; mi < 4; mi++)
#pragma unroll
                for (int ni = 0; ni < 4; ni++)
                    mma_f16(acc[mi][ni], a[mi][0], a[mi][1], a[mi][2], a[mi][3],
                            b[ni >> 1][2 * (ni & 1)], b[ni >> 1][2 * (ni & 1) + 1]);
        }
    }
#undef STAGE

    // ---- epilogue: descale, store logits, direct per-(row,32-col-group) max ----
#pragma unroll
    for (int mi = 0; mi < 4; mi++) {
        const int rbase = rowBase + warpM * 64 + mi * 16 + (lane >> 2);
#pragma unroll
        for (int h = 0; h < 2; h++) {
            const int row = rbase + h * 8;
            float* cr = C + (size_t)row * KCB + colBase + warpN * 32 + (lane & 3) * 2;
            unsigned long long packed = 0ull;
#pragma unroll
            for (int ni = 0; ni < 4; ni++) {
                float v0 = acc[mi][ni][h * 2] * INV_BSCALE;
                float v1 = acc[mi][ni][h * 2 + 1] * INV_BSCALE;
                *(float2*)(cr + ni * 8) = make_float2(v0, v1);
                int col0 = colBase + warpN * 32 + ni * 8 + (lane & 3) * 2;
                unsigned long long p0 =
                    ((unsigned long long)f2ord(v0) << 32) | (unsigned int)(KCB - 1 - col0);
                unsigned long long p1 =
                    ((unsigned long long)f2ord(v1) << 32) | (unsigned int)(KCB - 2 - col0);
                if (p0 > packed) packed = p0;
                if (p1 > packed) packed = p1;
            }
#pragma unroll
            for (int off = 1; off <= 2; off <<= 1) {
                unsigned long long o = __shfl_xor_sync(0xffffffffu, packed, off);
                if (o > packed) packed = o;
            }
            if ((lane & 3) == 0)
                g_groupmax[(size_t)row * NGROUPS + (colBase >> 5) + warpN] = packed;
        }
    }
}

// -------- refine: warp/row, groupmax prune, skip rescore if single candidate --------
__global__ __launch_bounds__(256)
void refine_kernel(const float* __restrict__ A, const float* __restrict__ B,
                   const float* __restrict__ C, float* __restrict__ idx_out) {
    const int n = (blockIdx.x * blockDim.x + threadIdx.x) >> 5;
    const int lane = threadIdx.x & 31;
    if (n >= NROWS) return;

    const unsigned long long* gm = g_groupmax + (size_t)n * NGROUPS;
    unsigned long long pm[4];
#pragma unroll
    for (int j = 0; j < 4; j++) pm[j] = gm[lane + 32 * j];

    unsigned long long mx = pm[0];
#pragma unroll
    for (int j = 1; j < 4; j++) if (pm[j] > mx) mx = pm[j];
#pragma unroll
    for (int o = 16; o >= 1; o >>= 1) {
        unsigned long long t = __shfl_xor_sync(0xffffffffu, mx, o);
        if (t > mx) mx = t;
    }
    const float thr = ord2f((unsigned int)(mx >> 32)) - MARGIN;
    const float* crow = C + (size_t)n * KCB;

    // pass 1: count candidates
    int totalc = 0;
#pragma unroll
    for (int j = 0; j < 4; j++) {
        unsigned gmask = __ballot_sync(0xffffffffu, ord2f((unsigned int)(pm[j] >> 32)) >= thr);
        while (gmask) {
            int src = __ffs(gmask) - 1;
            gmask &= gmask - 1;
            int g = 32 * j + src;
            float v = crow[g * 32 + lane];
            totalc += __popc(__ballot_sync(0xffffffffu, v >= thr));
        }
    }

    int bestC;
    if (totalc <= 1) {
        bestC = KCB - 1 - (int)(unsigned int)(mx & 0xffffffffull);
    } else {
        float bestV = -3.4e38f;
        bestC = KCB;
        const float* zrow = A + (size_t)n * DDIM;
#pragma unroll
        for (int j = 0; j < 4; j++) {
            unsigned gmask = __ballot_sync(0xffffffffu, ord2f((unsigned int)(pm[j] >> 32)) >= thr);
            while (gmask) {
                int src = __ffs(gmask) - 1;
                gmask &= gmask - 1;
                int g = 32 * j + src;
                float v = crow[g * 32 + lane];
                unsigned cmask = __ballot_sync(0xffffffffu, v >= thr);
                while (cmask) {
                    int cs = __ffs(cmask) - 1;
                    cmask &= cmask - 1;
                    int cc = g * 32 + cs;
                    const float* brow = B + (size_t)cc * DDIM;
                    float acc = 0.0f;
#pragma unroll
                    for (int q = 0; q < 16; q++)
                        acc = fmaf(zrow[lane + 32 * q], brow[lane + 32 * q], acc);
#pragma unroll
                    for (int o = 16; o >= 1; o >>= 1)
                        acc += __shfl_xor_sync(0xffffffffu, acc, o);
                    if (acc > bestV || (acc == bestV && cc < bestC)) { bestV = acc; bestC = cc; }
                }
            }
        }
    }
    if (lane == 0) idx_out[n] = (float)bestC;
}

// -------- launch --------
extern "C" void kernel_launch(void* const* d_in, const int* in_sizes, int n_in,
                              void* d_out, int out_size) {
    const float* z  = (const float*)d_in[0];   // [32768, 512]
    const float* cb = (const float*)d_in[1];   // [4096, 512]
    float* out = (float*)d_out;
    float* logits = out;
    float* idx_out = out + ((size_t)out_size - NROWS);

    cudaFuncSetAttribute(gemm_f16_kernel, cudaFuncAttributeMaxDynamicSharedMemorySize,
                         SMEM_TOTAL);

    size_t convN = A8 + B8;
    convert_kernel<<<(unsigned)((convN + 511) / 512), 512>>>(z, cb);

    dim3 grid(KCB / BN, NROWS / BM);  // (32, 256)
    gemm_f16_kernel<<<grid, NTHREADS, SMEM_TOTAL>>>(logits);

    refine_kernel<<<NROWS / 8, 256>>>(z, cb, logits, idx_out);
}

// round 9
// speedup vs baseline: 7.1348x; 1.0294x over previous
#include <cuda_runtime.h>
#include <cuda_fp16.h>
#include <cstdint>

#define NROWS 32768
#define KCB   4096
#define DDIM  512

#define BM 128
#define BN 128
#define BK 64                 // halves per chunk = 128 bytes = SW128 row
#define NKCH (DDIM / BK)      // 8
#define NTHREADS 128
#define MARGIN 1e-4f
#define BSCALE 4096.0f
#define INV_BSCALE (1.0f / 4096.0f)
#define NGROUPS (KCB / 32)    // 128

#define A_STAGE (BM * 128)    // 16384
#define B_STAGE (BN * 128)    // 16384
#define STAGE_BYTES (A_STAGE + B_STAGE)   // 32768
#define NSTAGE 3
#define SMEM_TOTAL (NSTAGE * STAGE_BYTES) // 98304

// -------- device scratch --------
__device__ __align__(16) __half gAh[(size_t)NROWS * DDIM];
__device__ __align__(16) __half gBh[(size_t)KCB * DDIM];           // pre-scaled by 4096
__device__ unsigned long long g_groupmax[(size_t)NROWS * NGROUPS]; // 33.5 MB

// -------- helpers --------
__device__ __forceinline__ uint32_t smem_u32(const void* p) {
    uint32_t a;
    asm("{ .reg .u64 t; cvta.to.shared.u64 t, %1; cvt.u32.u64 %0, t; }" : "=r"(a) : "l"(p));
    return a;
}
__device__ __forceinline__ uint32_t sw128(uint32_t b) { return b ^ ((b >> 3) & 0x70); }
__device__ __forceinline__ unsigned int f2ord(float f) {
    unsigned int u = __float_as_uint(f);
    return (u & 0x80000000u) ? ~u : (u | 0x80000000u);
}
__device__ __forceinline__ float ord2f(unsigned int o) {
    unsigned int u = (o & 0x80000000u) ? (o & 0x7FFFFFFFu) : ~o;
    return __uint_as_float(u);
}
__device__ __forceinline__ void cp_async16(uint32_t s, const void* g) {
    asm volatile("cp.async.cg.shared.global [%0], [%1], 16;"
                 :: "r"(s), "l"(__cvta_generic_to_global(g)));
}
__device__ __forceinline__ void cp_commit() { asm volatile("cp.async.commit_group;" ::: "memory"); }
template <int N> __device__ __forceinline__ void cp_wait() {
    asm volatile("cp.async.wait_group %0;" :: "n"(N) : "memory");
}
__device__ __forceinline__ void ldm_x4(uint32_t& r0, uint32_t& r1, uint32_t& r2, uint32_t& r3,
                                       uint32_t addr) {
    asm volatile("ldmatrix.sync.aligned.m8n8.x4.shared.b16 {%0,%1,%2,%3}, [%4];"
                 : "=r"(r0), "=r"(r1), "=r"(r2), "=r"(r3) : "r"(addr));
}
__device__ __forceinline__ void mma_f16(float* c, uint32_t a0, uint32_t a1, uint32_t a2,
                                        uint32_t a3, uint32_t b0, uint32_t b1) {
    asm volatile(
        "mma.sync.aligned.m16n8k16.row.col.f32.f16.f16.f32 "
        "{%0,%1,%2,%3}, {%4,%5,%6,%7}, {%8,%9}, {%0,%1,%2,%3};"
        : "+f"(c[0]), "+f"(c[1]), "+f"(c[2]), "+f"(c[3])
        : "r"(a0), "r"(a1), "r"(a2), "r"(a3), "r"(b0), "r"(b1));
}
__device__ __forceinline__ uint32_t h2u(__half2 h) { return *reinterpret_cast<uint32_t*>(&h); }

// -------- convert (split A/B for profiling visibility + tuned grids) --------
#define A8 ((size_t)NROWS * DDIM / 8)
#define B8 ((size_t)KCB * DDIM / 8)

__global__ __launch_bounds__(512)
void convertA_kernel(const float* __restrict__ A) {
    size_t id = (size_t)blockIdx.x * blockDim.x + threadIdx.x;
    if (id < A8) {
        float4 f0 = ((const float4*)A)[2 * id];
        float4 f1 = ((const float4*)A)[2 * id + 1];
        uint4 o;
        o.x = h2u(__float22half2_rn(make_float2(f0.x, f0.y)));
        o.y = h2u(__float22half2_rn(make_float2(f0.z, f0.w)));
        o.z = h2u(__float22half2_rn(make_float2(f1.x, f1.y)));
        o.w = h2u(__float22half2_rn(make_float2(f1.z, f1.w)));
        ((uint4*)gAh)[id] = o;
    }
}

__global__ __launch_bounds__(512)
void convertB_kernel(const float* __restrict__ B) {
    size_t j = (size_t)blockIdx.x * blockDim.x + threadIdx.x;
    if (j < B8) {
        float4 f0 = ((const float4*)B)[2 * j];
        float4 f1 = ((const float4*)B)[2 * j + 1];
        uint4 o;
        o.x = h2u(__float22half2_rn(make_float2(f0.x * BSCALE, f0.y * BSCALE)));
        o.y = h2u(__float22half2_rn(make_float2(f0.z * BSCALE, f0.w * BSCALE)));
        o.z = h2u(__float22half2_rn(make_float2(f1.x * BSCALE, f1.y * BSCALE)));
        o.w = h2u(__float22half2_rn(make_float2(f1.z * BSCALE, f1.w * BSCALE)));
        ((uint4*)gBh)[j] = o;
    }
}

// -------- GEMM: 128x128 tile, 4 warps of 64x64, 2 CTAs/SM --------
__global__ __launch_bounds__(NTHREADS, 2)
void gemm_f16_kernel(float* __restrict__ C) {
    extern __shared__ char smem[];
    const uint32_t sbase = smem_u32(smem);
    const int tid = threadIdx.x;
    const int wid = tid >> 5;
    const int lane = tid & 31;
    const int warpM = wid >> 1;   // 0..1
    const int warpN = wid & 1;    // 0..1

    const int rowBase = blockIdx.y * BM;
    const int colBase = blockIdx.x * BN;

    // staging addresses: 8 A + 8 B transfers per thread (1024 x 16B each tile)
    int rIdx[8];
    uint32_t swOff[8];
    int c8[8];
#pragma unroll
    for (int i = 0; i < 8; i++) {
        int idx = tid + i * NTHREADS;           // 0..1023
        rIdx[i] = idx >> 3;
        swOff[i] = sw128((idx >> 3) * 128 + (idx & 7) * 16);
        c8[i] = idx & 7;
    }

#define STAGE(ks_, st_)                                                                   \
    do {                                                                                  \
        uint32_t base_ = sbase + (st_) * STAGE_BYTES;                                     \
        _Pragma("unroll")                                                                 \
        for (int i_ = 0; i_ < 8; i_++)                                                    \
            cp_async16(base_ + swOff[i_],                                                 \
                       gAh + (size_t)(rowBase + rIdx[i_]) * DDIM + (ks_) * BK + c8[i_] * 8); \
        _Pragma("unroll")                                                                 \
        for (int i_ = 0; i_ < 8; i_++)                                                    \
            cp_async16(base_ + A_STAGE + swOff[i_],                                       \
                       gBh + (size_t)(colBase + rIdx[i_]) * DDIM + (ks_) * BK + c8[i_] * 8); \
        cp_commit();                                                                      \
    } while (0)

    // fragment addressing (byte math within 128B SW128 rows)
    const int aRowOff = (lane & 7) | (((lane >> 3) & 1) << 3);
    const int aColSel = (lane >> 4) << 4;
    const int bRowOff = (lane & 7) | (((lane >> 4) & 1) << 3);
    const int bColSel = ((lane >> 3) & 1) << 4;

    uint32_t aBase[4], aXor[4], bBase[4], bXor[4];
#pragma unroll
    for (int mi = 0; mi < 4; mi++) {
        int r = warpM * 64 + mi * 16 + aRowOff;
        aBase[mi] = r * 128;
        aXor[mi] = (r & 7) << 4;
    }
#pragma unroll
    for (int p = 0; p < 4; p++) {
        int r = warpN * 64 + p * 16 + bRowOff;
        bBase[p] = A_STAGE + r * 128;
        bXor[p] = (r & 7) << 4;
    }

    float acc[4][8][4];
#pragma unroll
    for (int mi = 0; mi < 4; mi++)
#pragma unroll
        for (int nj = 0; nj < 8; nj++)
#pragma unroll
            for (int r = 0; r < 4; r++) acc[mi][nj][r] = 0.0f;

    STAGE(0, 0);
    STAGE(1, 1);

#pragma unroll
    for (int ks = 0; ks < NKCH; ks++) {
        if (ks < NKCH - 1) cp_wait<1>(); else cp_wait<0>();
        __syncthreads();
        if (ks + 2 < NKCH) STAGE(ks + 2, (ks + 2) % NSTAGE);

        const uint32_t buf = sbase + (ks % NSTAGE) * STAGE_BYTES;
#pragma unroll
        for (int kk = 0; kk < 4; kk++) {
            uint32_t a[4][4], b[4][4];
#pragma unroll
            for (int mi = 0; mi < 4; mi++)
                ldm_x4(a[mi][0], a[mi][1], a[mi][2], a[mi][3],
                       buf + aBase[mi] + (((uint32_t)(kk * 32 + aColSel)) ^ aXor[mi]));
#pragma unroll
            for (int p = 0; p < 4; p++)
                ldm_x4(b[p][0], b[p][1], b[p][2], b[p][3],
                       buf + bBase[p] + (((uint32_t)(kk * 32 + bColSel)) ^ bXor[p]));
#pragma unroll
            for (int mi = 0; mi < 4; mi++)
#pragma unroll
                for (int nj = 0; nj < 8; nj++)
                    mma_f16(acc[mi][nj], a[mi][0], a[mi][1], a[mi][2], a[mi][3],
                            b[nj >> 1][2 * (nj & 1)], b[nj >> 1][2 * (nj & 1) + 1]);
        }
    }
#undef STAGE

    // ---- epilogue: descale, store logits, direct per-(row,32-col-group) max ----
#pragma unroll
    for (int mi = 0; mi < 4; mi++) {
        const int rbase = rowBase + warpM * 64 + mi * 16 + (lane >> 2);
#pragma unroll
        for (int h = 0; h < 2; h++) {
            const int row = rbase + h * 8;
            float* cr = C + (size_t)row * KCB + colBase + warpN * 64 + (lane & 3) * 2;
#pragma unroll
            for (int g = 0; g < 2; g++) {
                unsigned long long packed = 0ull;
#pragma unroll
                for (int q = 0; q < 4; q++) {
                    const int nj = g * 4 + q;
                    float v0 = acc[mi][nj][h * 2] * INV_BSCALE;
                    float v1 = acc[mi][nj][h * 2 + 1] * INV_BSCALE;
                    *(float2*)(cr + nj * 8) = make_float2(v0, v1);
                    int col0 = colBase + warpN * 64 + nj * 8 + (lane & 3) * 2;
                    unsigned long long p0 =
                        ((unsigned long long)f2ord(v0) << 32) | (unsigned int)(KCB - 1 - col0);
                    unsigned long long p1 =
                        ((unsigned long long)f2ord(v1) << 32) | (unsigned int)(KCB - 2 - col0);
                    if (p0 > packed) packed = p0;
                    if (p1 > packed) packed = p1;
                }
#pragma unroll
                for (int off = 1; off <= 2; off <<= 1) {
                    unsigned long long o = __shfl_xor_sync(0xffffffffu, packed, off);
                    if (o > packed) packed = o;
                }
                if ((lane & 3) == 0)
                    g_groupmax[(size_t)row * NGROUPS + ((colBase + warpN * 64) >> 5) + g] = packed;
            }
        }
    }
}

// -------- refine: warp/row, groupmax prune, skip rescore if single candidate --------
__global__ __launch_bounds__(256)
void refine_kernel(const float* __restrict__ A, const float* __restrict__ B,
                   const float* __restrict__ C, float* __restrict__ idx_out) {
    const int n = (blockIdx.x * blockDim.x + threadIdx.x) >> 5;
    const int lane = threadIdx.x & 31;
    if (n >= NROWS) return;

    const unsigned long long* gm = g_groupmax + (size_t)n * NGROUPS;
    unsigned long long pm[4];
#pragma unroll
    for (int j = 0; j < 4; j++) pm[j] = gm[lane + 32 * j];

    unsigned long long mx = pm[0];
#pragma unroll
    for (int j = 1; j < 4; j++) if (pm[j] > mx) mx = pm[j];
#pragma unroll
    for (int o = 16; o >= 1; o >>= 1) {
        unsigned long long t = __shfl_xor_sync(0xffffffffu, mx, o);
        if (t > mx) mx = t;
    }
    const float thr = ord2f((unsigned int)(mx >> 32)) - MARGIN;
    const float* crow = C + (size_t)n * KCB;

    // pass 1: count candidates
    int totalc = 0;
#pragma unroll
    for (int j = 0; j < 4; j++) {
        unsigned gmask = __ballot_sync(0xffffffffu, ord2f((unsigned int)(pm[j] >> 32)) >= thr);
        while (gmask) {
            int src = __ffs(gmask) - 1;
            gmask &= gmask - 1;
            int g = 32 * j + src;
            float v = crow[g * 32 + lane];
            totalc += __popc(__ballot_sync(0xffffffffu, v >= thr));
        }
    }

    int bestC;
    if (totalc <= 1) {
        bestC = KCB - 1 - (int)(unsigned int)(mx & 0xffffffffull);
    } else {
        float bestV = -3.4e38f;
        bestC = KCB;
        const float* zrow = A + (size_t)n * DDIM;
#pragma unroll
        for (int j = 0; j < 4; j++) {
            unsigned gmask = __ballot_sync(0xffffffffu, ord2f((unsigned int)(pm[j] >> 32)) >= thr);
            while (gmask) {
                int src = __ffs(gmask) - 1;
                gmask &= gmask - 1;
                int g = 32 * j + src;
                float v = crow[g * 32 + lane];
                unsigned cmask = __ballot_sync(0xffffffffu, v >= thr);
                while (cmask) {
                    int cs = __ffs(cmask) - 1;
                    cmask &= cmask - 1;
                    int cc = g * 32 + cs;
                    const float* brow = B + (size_t)cc * DDIM;
                    float acc = 0.0f;
#pragma unroll
                    for (int q = 0; q < 16; q++)
                        acc = fmaf(zrow[lane + 32 * q], brow[lane + 32 * q], acc);
#pragma unroll
                    for (int o = 16; o >= 1; o >>= 1)
                        acc += __shfl_xor_sync(0xffffffffu, acc, o);
                    if (acc > bestV || (acc == bestV && cc < bestC)) { bestV = acc; bestC = cc; }
                }
            }
        }
    }
    if (lane == 0) idx_out[n] = (float)bestC;
}

// -------- launch --------
extern "C" void kernel_launch(void* const* d_in, const int* in_sizes, int n_in,
                              void* d_out, int out_size) {
    const float* z  = (const float*)d_in[0];   // [32768, 512]
    const float* cb = (const float*)d_in[1];   // [4096, 512]
    float* out = (float*)d_out;
    float* logits = out;
    float* idx_out = out + ((size_t)out_size - NROWS);

    cudaFuncSetAttribute(gemm_f16_kernel, cudaFuncAttributeMaxDynamicSharedMemorySize,
                         SMEM_TOTAL);

    convertA_kernel<<<(unsigned)((A8 + 511) / 512), 512>>>(z);
    convertB_kernel<<<(unsigned)((B8 + 511) / 512), 512>>>(cb);

    dim3 grid(KCB / BN, NROWS / BM);  // (32, 256)
    gemm_f16_kernel<<<grid, NTHREADS, SMEM_TOTAL>>>(logits);

    refine_kernel<<<NROWS / 8, 256>>>(z, cb, logits, idx_out);
}

// round 10
// speedup vs baseline: 7.1641x; 1.0041x over previous
#include <cuda_runtime.h>
#include <cuda_fp16.h>
#include <cstdint>

#define NROWS 32768
#define KCB   4096
#define DDIM  512

#define BM 128
#define BN 128
#define BK 64                 // halves per chunk = 128 bytes = SW128 row
#define NKCH (DDIM / BK)      // 8
#define NTHREADS 128
#define MARGIN 1e-4f
#define BSCALE 4096.0f
#define INV_BSCALE (1.0f / 4096.0f)
#define NGROUPS (KCB / 32)    // 128

#define A_STAGE (BM * 128)    // 16384
#define B_STAGE (BN * 128)    // 16384
#define STAGE_BYTES (A_STAGE + B_STAGE)   // 32768
#define NSTAGE 3
#define SMEM_TOTAL (NSTAGE * STAGE_BYTES) // 98304

// -------- device scratch --------
__device__ __align__(16) __half gAh[(size_t)NROWS * DDIM];
__device__ __align__(16) __half gBh[(size_t)KCB * DDIM];           // pre-scaled by 4096
__device__ unsigned long long g_groupmax[(size_t)NROWS * NGROUPS]; // 33.5 MB

// -------- helpers --------
__device__ __forceinline__ uint32_t smem_u32(const void* p) {
    uint32_t a;
    asm("{ .reg .u64 t; cvta.to.shared.u64 t, %1; cvt.u32.u64 %0, t; }" : "=r"(a) : "l"(p));
    return a;
}
__device__ __forceinline__ uint32_t sw128(uint32_t b) { return b ^ ((b >> 3) & 0x70); }
__device__ __forceinline__ unsigned int f2ord(float f) {
    unsigned int u = __float_as_uint(f);
    return (u & 0x80000000u) ? ~u : (u | 0x80000000u);
}
__device__ __forceinline__ float ord2f(unsigned int o) {
    unsigned int u = (o & 0x80000000u) ? (o & 0x7FFFFFFFu) : ~o;
    return __uint_as_float(u);
}
__device__ __forceinline__ void cp_async16(uint32_t s, const void* g) {
    asm volatile("cp.async.cg.shared.global [%0], [%1], 16;"
                 :: "r"(s), "l"(__cvta_generic_to_global(g)));
}
__device__ __forceinline__ void cp_commit() { asm volatile("cp.async.commit_group;" ::: "memory"); }
template <int N> __device__ __forceinline__ void cp_wait() {
    asm volatile("cp.async.wait_group %0;" :: "n"(N) : "memory");
}
__device__ __forceinline__ void ldm_x4(uint32_t& r0, uint32_t& r1, uint32_t& r2, uint32_t& r3,
                                       uint32_t addr) {
    asm volatile("ldmatrix.sync.aligned.m8n8.x4.shared.b16 {%0,%1,%2,%3}, [%4];"
                 : "=r"(r0), "=r"(r1), "=r"(r2), "=r"(r3) : "r"(addr));
}
__device__ __forceinline__ void mma_f16(float* c, uint32_t a0, uint32_t a1, uint32_t a2,
                                        uint32_t a3, uint32_t b0, uint32_t b1) {
    asm volatile(
        "mma.sync.aligned.m16n8k16.row.col.f32.f16.f16.f32 "
        "{%0,%1,%2,%3}, {%4,%5,%6,%7}, {%8,%9}, {%0,%1,%2,%3};"
        : "+f"(c[0]), "+f"(c[1]), "+f"(c[2]), "+f"(c[3])
        : "r"(a0), "r"(a1), "r"(a2), "r"(a3), "r"(b0), "r"(b1));
}
__device__ __forceinline__ uint32_t h2u(__half2 h) { return *reinterpret_cast<uint32_t*>(&h); }

// -------- convert --------
#define A8 ((size_t)NROWS * DDIM / 8)
#define B8 ((size_t)KCB * DDIM / 8)

__global__ __launch_bounds__(512)
void convertA_kernel(const float* __restrict__ A) {
    size_t id = (size_t)blockIdx.x * blockDim.x + threadIdx.x;
    if (id < A8) {
        float4 f0 = ((const float4*)A)[2 * id];
        float4 f1 = ((const float4*)A)[2 * id + 1];
        uint4 o;
        o.x = h2u(__float22half2_rn(make_float2(f0.x, f0.y)));
        o.y = h2u(__float22half2_rn(make_float2(f0.z, f0.w)));
        o.z = h2u(__float22half2_rn(make_float2(f1.x, f1.y)));
        o.w = h2u(__float22half2_rn(make_float2(f1.z, f1.w)));
        ((uint4*)gAh)[id] = o;
    }
}

__global__ __launch_bounds__(512)
void convertB_kernel(const float* __restrict__ B) {
    size_t j = (size_t)blockIdx.x * blockDim.x + threadIdx.x;
    if (j < B8) {
        float4 f0 = ((const float4*)B)[2 * j];
        float4 f1 = ((const float4*)B)[2 * j + 1];
        uint4 o;
        o.x = h2u(__float22half2_rn(make_float2(f0.x * BSCALE, f0.y * BSCALE)));
        o.y = h2u(__float22half2_rn(make_float2(f0.z * BSCALE, f0.w * BSCALE)));
        o.z = h2u(__float22half2_rn(make_float2(f1.x * BSCALE, f1.y * BSCALE)));
        o.w = h2u(__float22half2_rn(make_float2(f1.z * BSCALE, f1.w * BSCALE)));
        ((uint4*)gBh)[j] = o;
    }
}

// -------- GEMM: 128x128 tile, 4 warps of 64x64, 2 CTAs/SM, reg-double-buffered --------
__global__ __launch_bounds__(NTHREADS, 2)
void gemm_f16_kernel(float* __restrict__ C) {
    extern __shared__ char smem[];
    const uint32_t sbase = smem_u32(smem);
    const int tid = threadIdx.x;
    const int wid = tid >> 5;
    const int lane = tid & 31;
    const int warpM = wid >> 1;   // 0..1
    const int warpN = wid & 1;    // 0..1

    const int rowBase = blockIdx.y * BM;
    const int colBase = blockIdx.x * BN;

    // staging addresses: 8 A + 8 B transfers per thread
    int rIdx[8];
    uint32_t swOff[8];
    int c8[8];
#pragma unroll
    for (int i = 0; i < 8; i++) {
        int idx = tid + i * NTHREADS;           // 0..1023
        rIdx[i] = idx >> 3;
        swOff[i] = sw128((idx >> 3) * 128 + (idx & 7) * 16);
        c8[i] = idx & 7;
    }

#define STAGE(ks_, st_)                                                                   \
    do {                                                                                  \
        uint32_t base_ = sbase + (st_) * STAGE_BYTES;                                     \
        _Pragma("unroll")                                                                 \
        for (int i_ = 0; i_ < 8; i_++)                                                    \
            cp_async16(base_ + swOff[i_],                                                 \
                       gAh + (size_t)(rowBase + rIdx[i_]) * DDIM + (ks_) * BK + c8[i_] * 8); \
        _Pragma("unroll")                                                                 \
        for (int i_ = 0; i_ < 8; i_++)                                                    \
            cp_async16(base_ + A_STAGE + swOff[i_],                                       \
                       gBh + (size_t)(colBase + rIdx[i_]) * DDIM + (ks_) * BK + c8[i_] * 8); \
        cp_commit();                                                                      \
    } while (0)

    // fragment addressing (byte math within 128B SW128 rows)
    const int aRowOff = (lane & 7) | (((lane >> 3) & 1) << 3);
    const int aColSel = (lane >> 4) << 4;
    const int bRowOff = (lane & 7) | (((lane >> 4) & 1) << 3);
    const int bColSel = ((lane >> 3) & 1) << 4;

    uint32_t aBase[4], aXor[4], bBase[4], bXor[4];
#pragma unroll
    for (int mi = 0; mi < 4; mi++) {
        int r = warpM * 64 + mi * 16 + aRowOff;
        aBase[mi] = r * 128;
        aXor[mi] = (r & 7) << 4;
    }
#pragma unroll
    for (int p = 0; p < 4; p++) {
        int r = warpN * 64 + p * 16 + bRowOff;
        bBase[p] = A_STAGE + r * 128;
        bXor[p] = (r & 7) << 4;
    }

    float acc[4][8][4];
#pragma unroll
    for (int mi = 0; mi < 4; mi++)
#pragma unroll
        for (int nj = 0; nj < 8; nj++)
#pragma unroll
            for (int r = 0; r < 4; r++) acc[mi][nj][r] = 0.0f;

    STAGE(0, 0);
    STAGE(1, 1);

    uint32_t af[2][4][4], bf[2][4][4];

#define LOADFRAG(dst_, buf_, kk_)                                                          \
    do {                                                                                   \
        _Pragma("unroll")                                                                  \
        for (int mi_ = 0; mi_ < 4; mi_++)                                                  \
            ldm_x4(af[dst_][mi_][0], af[dst_][mi_][1], af[dst_][mi_][2], af[dst_][mi_][3], \
                   (buf_) + aBase[mi_] + (((uint32_t)((kk_) * 32 + aColSel)) ^ aXor[mi_]));\
        _Pragma("unroll")                                                                  \
        for (int p_ = 0; p_ < 4; p_++)                                                     \
            ldm_x4(bf[dst_][p_][0], bf[dst_][p_][1], bf[dst_][p_][2], bf[dst_][p_][3],     \
                   (buf_) + bBase[p_] + (((uint32_t)((kk_) * 32 + bColSel)) ^ bXor[p_]));  \
    } while (0)

#pragma unroll
    for (int ks = 0; ks < NKCH; ks++) {
        if (ks < NKCH - 1) cp_wait<1>(); else cp_wait<0>();
        __syncthreads();
        if (ks + 2 < NKCH) STAGE(ks + 2, (ks + 2) % NSTAGE);

        const uint32_t buf = sbase + (ks % NSTAGE) * STAGE_BYTES;

        LOADFRAG(0, buf, 0);
#pragma unroll
        for (int kk = 0; kk < 4; kk++) {
            const int cur = kk & 1;
            if (kk < 3) LOADFRAG(cur ^ 1, buf, kk + 1);
#pragma unroll
            for (int mi = 0; mi < 4; mi++)
#pragma unroll
                for (int nj = 0; nj < 8; nj++)
                    mma_f16(acc[mi][nj], af[cur][mi][0], af[cur][mi][1], af[cur][mi][2],
                            af[cur][mi][3], bf[cur][nj >> 1][2 * (nj & 1)],
                            bf[cur][nj >> 1][2 * (nj & 1) + 1]);
        }
    }
#undef STAGE
#undef LOADFRAG

    // ---- epilogue: descale, store logits, direct per-(row,32-col-group) max ----
#pragma unroll
    for (int mi = 0; mi < 4; mi++) {
        const int rbase = rowBase + warpM * 64 + mi * 16 + (lane >> 2);
#pragma unroll
        for (int h = 0; h < 2; h++) {
            const int row = rbase + h * 8;
            float* cr = C + (size_t)row * KCB + colBase + warpN * 64 + (lane & 3) * 2;
#pragma unroll
            for (int g = 0; g < 2; g++) {
                unsigned long long packed = 0ull;
#pragma unroll
                for (int q = 0; q < 4; q++) {
                    const int nj = g * 4 + q;
                    float v0 = acc[mi][nj][h * 2] * INV_BSCALE;
                    float v1 = acc[mi][nj][h * 2 + 1] * INV_BSCALE;
                    *(float2*)(cr + nj * 8) = make_float2(v0, v1);
                    int col0 = colBase + warpN * 64 + nj * 8 + (lane & 3) * 2;
                    unsigned long long p0 =
                        ((unsigned long long)f2ord(v0) << 32) | (unsigned int)(KCB - 1 - col0);
                    unsigned long long p1 =
                        ((unsigned long long)f2ord(v1) << 32) | (unsigned int)(KCB - 2 - col0);
                    if (p0 > packed) packed = p0;
                    if (p1 > packed) packed = p1;
                }
#pragma unroll
                for (int off = 1; off <= 2; off <<= 1) {
                    unsigned long long o = __shfl_xor_sync(0xffffffffu, packed, off);
                    if (o > packed) packed = o;
                }
                if ((lane & 3) == 0)
                    g_groupmax[(size_t)row * NGROUPS + ((colBase + warpN * 64) >> 5) + g] = packed;
            }
        }
    }
}

// -------- refine: warp/row, groupmax prune, skip rescore if single candidate --------
__global__ __launch_bounds__(256)
void refine_kernel(const float* __restrict__ A, const float* __restrict__ B,
                   const float* __restrict__ C, float* __restrict__ idx_out) {
    const int n = (blockIdx.x * blockDim.x + threadIdx.x) >> 5;
    const int lane = threadIdx.x & 31;
    if (n >= NROWS) return;

    const unsigned long long* gm = g_groupmax + (size_t)n * NGROUPS;
    unsigned long long pm[4];
#pragma unroll
    for (int j = 0; j < 4; j++) pm[j] = gm[lane + 32 * j];

    unsigned long long mx = pm[0];
#pragma unroll
    for (int j = 1; j < 4; j++) if (pm[j] > mx) mx = pm[j];
#pragma unroll
    for (int o = 16; o >= 1; o >>= 1) {
        unsigned long long t = __shfl_xor_sync(0xffffffffu, mx, o);
        if (t > mx) mx = t;
    }
    const float thr = ord2f((unsigned int)(mx >> 32)) - MARGIN;
    const float* crow = C + (size_t)n * KCB;

    // pass 1: count candidates
    int totalc = 0;
#pragma unroll
    for (int j = 0; j < 4; j++) {
        unsigned gmask = __ballot_sync(0xffffffffu, ord2f((unsigned int)(pm[j] >> 32)) >= thr);
        while (gmask) {
            int src = __ffs(gmask) - 1;
            gmask &= gmask - 1;
            int g = 32 * j + src;
            float v = crow[g * 32 + lane];
            totalc += __popc(__ballot_sync(0xffffffffu, v >= thr));
        }
    }

    int bestC;
    if (totalc <= 1) {
        bestC = KCB - 1 - (int)(unsigned int)(mx & 0xffffffffull);
    } else {
        float bestV = -3.4e38f;
        bestC = KCB;
        const float* zrow = A + (size_t)n * DDIM;
#pragma unroll
        for (int j = 0; j < 4; j++) {
            unsigned gmask = __ballot_sync(0xffffffffu, ord2f((unsigned int)(pm[j] >> 32)) >= thr);
            while (gmask) {
                int src = __ffs(gmask) - 1;
                gmask &= gmask - 1;
                int g = 32 * j + src;
                float v = crow[g * 32 + lane];
                unsigned cmask = __ballot_sync(0xffffffffu, v >= thr);
                while (cmask) {
                    int cs = __ffs(cmask) - 1;
                    cmask &= cmask - 1;
                    int cc = g * 32 + cs;
                    const float* brow = B + (size_t)cc * DDIM;
                    float acc = 0.0f;
#pragma unroll
                    for (int q = 0; q < 16; q++)
                        acc = fmaf(zrow[lane + 32 * q], brow[lane + 32 * q], acc);
#pragma unroll
                    for (int o = 16; o >= 1; o >>= 1)
                        acc += __shfl_xor_sync(0xffffffffu, acc, o);
                    if (acc > bestV || (acc == bestV && cc < bestC)) { bestV = acc; bestC = cc; }
                }
            }
        }
    }
    if (lane == 0) idx_out[n] = (float)bestC;
}

// -------- launch --------
extern "C" void kernel_launch(void* const* d_in, const int* in_sizes, int n_in,
                              void* d_out, int out_size) {
    const float* z  = (const float*)d_in[0];   // [32768, 512]
    const float* cb = (const float*)d_in[1];   // [4096, 512]
    float* out = (float*)d_out;
    float* logits = out;
    float* idx_out = out + ((size_t)out_size - NROWS);

    cudaFuncSetAttribute(gemm_f16_kernel, cudaFuncAttributeMaxDynamicSharedMemorySize,
                         SMEM_TOTAL);

    convertA_kernel<<<(unsigned)((A8 + 511) / 512), 512>>>(z);
    convertB_kernel<<<(unsigned)((B8 + 511) / 512), 512>>>(cb);

    dim3 grid(KCB / BN, NROWS / BM);  // (32, 256)
    gemm_f16_kernel<<<grid, NTHREADS, SMEM_TOTAL>>>(logits);

    refine_kernel<<<NROWS / 8, 256>>>(z, cb, logits, idx_out);
}